// round 9
// baseline (speedup 1.0000x reference)
#include <cuda_runtime.h>
#include <cstdint>

#define BB 16
#define NN 1024
#define MM 12
#define FA 128
#define FO 128
#define US 132            // sU row stride in floats

// Scratch (allocation-free rule: __device__ globals)
__device__ float g_bn3[BB * NN];
__device__ float g_bn6[BB * NN];
__device__ int   g_is64;

// ---------------------------------------------------------------------------
// Kernel 1 (v4): one warp per FOUR (b,n) rows; 12 LDG.128 issued up front.
// prod_m(x_m / s) == (prod x_m) / s^12.
// ---------------------------------------------------------------------------
__global__ void bond_kernel(const float* __restrict__ bond,
                            const int* __restrict__ adj_raw) {
    // ---- dtype sniff: int64 indices < 1024 have all-zero odd 32-bit words
    if (blockIdx.x == 0 && threadIdx.x < 32) {
        int lane = threadIdx.x;
        bool odd_zero = true;
        #pragma unroll
        for (int j = 0; j < 32; j++) {
            int pair = lane + 32 * j;
            if (adj_raw[2 * pair + 1] != 0) odd_zero = false;
        }
        bool all = __all_sync(0xffffffffu, odd_zero);
        if (lane == 0) g_is64 = all ? 1 : 0;
    }

    int warp = (blockIdx.x * blockDim.x + threadIdx.x) >> 5;
    int lane = threadIdx.x & 31;
    int row0 = warp * 4;
    if (row0 >= BB * NN) return;

    const float4* p = (const float4*)(bond + (size_t)row0 * (MM * 32));
    float4 v[12];
    #pragma unroll
    for (int j = 0; j < 4; j++) {
        v[j * 3 + 0] = p[j * 96 + lane];
        v[j * 3 + 1] = p[j * 96 + lane + 32];
        v[j * 3 + 2] = p[j * 96 + lane + 64];
    }

    float q[12];
    #pragma unroll
    for (int t = 0; t < 12; t++)
        q[t] = v[t].x * v[t].x + v[t].y * v[t].y + v[t].z * v[t].z + v[t].w * v[t].w;

    #pragma unroll
    for (int o = 4; o >= 1; o >>= 1) {
        #pragma unroll
        for (int t = 0; t < 12; t++)
            q[t] += __shfl_xor_sync(0xffffffffu, q[t], o, 8);
    }

    float res[4];
    #pragma unroll
    for (int j = 0; j < 4; j++) {
        float x0 = 1.0f / q[j * 3 + 0];
        float x1 = 1.0f / q[j * 3 + 1];
        float x2 = 1.0f / q[j * 3 + 2];
        float s  = x0 + x1 + x2;
        float pr = x0 * x1 * x2;
        s  += __shfl_xor_sync(0xffffffffu, s, 8);
        s  += __shfl_xor_sync(0xffffffffu, s, 16);
        pr *= __shfl_xor_sync(0xffffffffu, pr, 8);
        pr *= __shfl_xor_sync(0xffffffffu, pr, 16);
        s = fmaxf(s, 1e-12f);
        float s2 = s * s, s4 = s2 * s2, s8 = s4 * s4;
        res[j] = pr / (s8 * s4);
    }

    if (lane == 0)
        *(float4*)(g_bn3 + row0) = make_float4(res[0], res[1], res[2], res[3]);
}

// ---------------------------------------------------------------------------
// Kernel 2 (unchanged): normalize over B, invert, normalize over N.
// ---------------------------------------------------------------------------
__global__ void norm_kernel() {
    int b = blockIdx.x;
    int n = threadIdx.x;

    float csum = 0.0f;
    #pragma unroll
    for (int bb = 0; bb < BB; bb++) csum += fabsf(g_bn3[bb * NN + n]);
    csum = fmaxf(csum, 1e-12f);

    float bn4 = g_bn3[b * NN + n] / csum;
    float bn5 = 1.0f / bn4;

    float r = fabsf(bn5);
    #pragma unroll
    for (int o = 16; o >= 1; o >>= 1) r += __shfl_xor_sync(0xffffffffu, r, o, 32);

    __shared__ float part[32];
    __shared__ float total;
    int wid = threadIdx.x >> 5, lane = threadIdx.x & 31;
    if (lane == 0) part[wid] = r;
    __syncthreads();
    if (wid == 0) {
        float v = part[lane];
        #pragma unroll
        for (int o = 16; o >= 1; o >>= 1) v += __shfl_xor_sync(0xffffffffu, v, o, 32);
        if (lane == 0) total = fmaxf(v, 1e-12f);
    }
    __syncthreads();

    g_bn6[b * NN + n] = bn5 / total;
}

// ---------------------------------------------------------------------------
// Kernel 3: producer/consumer warp-specialized gather + fp32 GEMM.
// 320 threads: warps 0-7 compute (2/SMSP -> FFMA-saturating), warps 8-9 gather.
// Each CTA: two 64-row tiles, sU double-buffered:
//   gather(t0); bar; { GEMM(t0)+epilogue || gather(t1) }; bar; GEMM(t1)+epi.
// ---------------------------------------------------------------------------
__device__ __forceinline__ void do_gather(const float* __restrict__ atomB,
                                          const int* __restrict__ adjB,
                                          const float* __restrict__ bn6B,
                                          int nbase, int gw, int lane,
                                          float* __restrict__ sUt, int stride) {
    #pragma unroll 2
    for (int i = 0; i < 32; i++) {
        int r = gw * 32 + i;
        int n = nbase + r;
        const int* adjr = adjB + (size_t)n * MM * stride;
        float4 a4 = *(const float4*)(atomB + n * FA + lane * 4);
        float sx = 0.f, sy = 0.f, sz = 0.f, sw = 0.f;
        #pragma unroll
        for (int m = 0; m < MM; m++) {
            int idx = adjr[m * stride] & (NN - 1);
            float4 v = *(const float4*)(atomB + idx * FA + lane * 4);
            sx += v.x; sy += v.y; sz += v.z; sw += v.w;
        }
        float sc = bn6B[n];
        const float inv12 = 1.0f / 12.0f;
        float4 u4;
        u4.x = (a4.x + sx * inv12) * sc;
        u4.y = (a4.y + sy * inv12) * sc;
        u4.z = (a4.z + sz * inv12) * sc;
        u4.w = (a4.w + sw * inv12) * sc;
        *(float4*)(sUt + (size_t)r * US + lane * 4) = u4;
    }
}

__device__ __forceinline__ void do_gemm(const float* __restrict__ sW,
                                        const float* __restrict__ sUt,
                                        const float* __restrict__ bias,
                                        float* __restrict__ outB,
                                        int nbase, int tid) {
    int ty = tid >> 4;        // 0..15 -> rows [ty*4, ty*4+4)
    int tx = tid & 15;        // 0..15 -> cols [tx*8, tx*8+8)
    int r0 = ty * 4;
    int c0 = tx * 8;

    float acc[4][8];
    #pragma unroll
    for (int i = 0; i < 4; i++)
        #pragma unroll
        for (int j = 0; j < 8; j++) acc[i][j] = 0.0f;

    #pragma unroll 4
    for (int k = 0; k < FA; k++) {
        float4 w0 = *(const float4*)(sW + k * FO + c0);
        float4 w1 = *(const float4*)(sW + k * FO + c0 + 4);
        float wc[8] = {w0.x, w0.y, w0.z, w0.w, w1.x, w1.y, w1.z, w1.w};
        float ur[4];
        #pragma unroll
        for (int i = 0; i < 4; i++) ur[i] = sUt[(size_t)(r0 + i) * US + k];
        #pragma unroll
        for (int i = 0; i < 4; i++)
            #pragma unroll
            for (int j = 0; j < 8; j++)
                acc[i][j] = fmaf(ur[i], wc[j], acc[i][j]);
    }

    float4 b0 = *(const float4*)(bias + c0);
    float4 b1 = *(const float4*)(bias + c0 + 4);
    float bc[8] = {b0.x, b0.y, b0.z, b0.w, b1.x, b1.y, b1.z, b1.w};

    #pragma unroll
    for (int i = 0; i < 4; i++) {
        int n = nbase + r0 + i;
        float4 o0, o1;
        o0.x = fmaxf(acc[i][0] + bc[0], 0.0f);
        o0.y = fmaxf(acc[i][1] + bc[1], 0.0f);
        o0.z = fmaxf(acc[i][2] + bc[2], 0.0f);
        o0.w = fmaxf(acc[i][3] + bc[3], 0.0f);
        o1.x = fmaxf(acc[i][4] + bc[4], 0.0f);
        o1.y = fmaxf(acc[i][5] + bc[5], 0.0f);
        o1.z = fmaxf(acc[i][6] + bc[6], 0.0f);
        o1.w = fmaxf(acc[i][7] + bc[7], 0.0f);
        float* op = outB + (size_t)n * FO + c0;
        *(float4*)(op)     = o0;
        *(float4*)(op + 4) = o1;
    }
}

#define SMEM_TOTAL ((FA * FO) * 4 + 2 * 64 * US * 4)   // 64KB W + 2x33.8KB U

__global__ void __launch_bounds__(320, 1)
main_kernel(const float* __restrict__ atom,
            const int* __restrict__ adj,
            const float* __restrict__ W,
            const float* __restrict__ bias,
            float* __restrict__ out) {
    extern __shared__ float smem[];
    float* sW  = smem;                   // 128x128
    float* sU0 = smem + FA * FO;         // tile 0: 64 x US
    float* sU1 = sU0 + 64 * US;          // tile 1

    int b    = blockIdx.y;
    int base = blockIdx.x * 128;         // this CTA covers rows base..base+127
    int tid  = threadIdx.x;
    int wid  = tid >> 5, lane = tid & 31;
    int stride = g_is64 ? 2 : 1;

    const float* atomB = atom + (size_t)b * NN * FA;
    const int*   adjB  = adj + (size_t)b * NN * MM * stride;
    const float* bn6B  = g_bn6 + b * NN;
    float*       outB  = out + (size_t)b * NN * FO;

    // Load W into smem (all 320 threads), coalesced float4
    {
        const float4* Wg = (const float4*)W;
        float4* sW4 = (float4*)sW;
        for (int i = tid; i < (FA * FO) / 4; i += 320) sW4[i] = Wg[i];
    }

    if (wid >= 8)
        do_gather(atomB, adjB, bn6B, base, wid - 8, lane, sU0, stride);
    __syncthreads();                     // sW + sU0 ready

    if (wid < 8)
        do_gemm(sW, sU0, bias, outB, base, tid);           // tile 0
    else
        do_gather(atomB, adjB, bn6B, base + 64, wid - 8, lane, sU1, stride);
    __syncthreads();                     // sU1 ready

    if (wid < 8)
        do_gemm(sW, sU1, bias, outB, base + 64, tid);      // tile 1
}

// ---------------------------------------------------------------------------
extern "C" void kernel_launch(void* const* d_in, const int* in_sizes, int n_in,
                              void* d_out, int out_size) {
    const float* atom = (const float*)d_in[0];
    const float* bond = (const float*)d_in[1];
    const int*   adj  = (const int*)d_in[2];
    const float* W    = (const float*)d_in[3];
    const float* bias = (const float*)d_in[4];
    float*       out  = (float*)d_out;

    // 4 rows per warp: 4096 warps = 512 blocks x 8 warps
    bond_kernel<<<512, 256>>>(bond, adj);
    norm_kernel<<<BB, NN>>>();

    cudaFuncSetAttribute(main_kernel, cudaFuncAttributeMaxDynamicSharedMemorySize,
                         SMEM_TOTAL);
    main_kernel<<<dim3(NN / 128, BB), 320, SMEM_TOTAL>>>(atom, adj, W, bias, out);
}

// round 11
// speedup vs baseline: 1.6725x; 1.6725x over previous
#include <cuda_runtime.h>
#include <cuda_fp16.h>
#include <cstdint>

#define BB 16
#define NN 1024
#define MM 12
#define FA 128
#define FO 128

// Scratch (allocation-free rule: __device__ globals)
__device__ float  g_bn3[BB * NN];
__device__ float  g_bn6[BB * NN];
__device__ __half g_atom_h[BB * NN * FA];   // 4 MB fp16 copy of atom
__device__ __half g_Wh[FA * FO];            // fp16 copy of W
__device__ int    g_is64;

// ---- bit-pun helpers (union-based; no exotic intrinsics) -------------------
__device__ __forceinline__ uint32_t h2_to_u(__half2 h) {
    union { __half2 h; uint32_t u; } c; c.h = h; return c.u;
}
__device__ __forceinline__ __half2 u_to_h2(uint32_t u) {
    union { uint32_t u; __half2 h; } c; c.u = u; return c.h;
}

// ---------------------------------------------------------------------------
// Kernel 1 (R7 version, best measured): one warp per TWO rows, 6 LDG.128.
// ---------------------------------------------------------------------------
__global__ void bond_kernel(const float* __restrict__ bond,
                            const int* __restrict__ adj_raw) {
    if (blockIdx.x == 0 && threadIdx.x < 32) {
        int lane = threadIdx.x;
        bool odd_zero = true;
        #pragma unroll
        for (int j = 0; j < 32; j++) {
            int pair = lane + 32 * j;
            if (adj_raw[2 * pair + 1] != 0) odd_zero = false;
        }
        bool all = __all_sync(0xffffffffu, odd_zero);
        if (lane == 0) g_is64 = all ? 1 : 0;
    }

    int warp = (blockIdx.x * blockDim.x + threadIdx.x) >> 5;
    int lane = threadIdx.x & 31;
    int row0 = warp * 2;
    if (row0 >= BB * NN) return;

    const float4* p0 = (const float4*)(bond + (size_t)row0 * (MM * 32));
    const float4* p1 = p0 + MM * 32 / 4;
    float4 a0 = p0[lane];
    float4 a1 = p0[lane + 32];
    float4 a2 = p0[lane + 64];
    float4 b0 = p1[lane];
    float4 b1 = p1[lane + 32];
    float4 b2 = p1[lane + 64];

    float qa0 = a0.x*a0.x + a0.y*a0.y + a0.z*a0.z + a0.w*a0.w;
    float qa1 = a1.x*a1.x + a1.y*a1.y + a1.z*a1.z + a1.w*a1.w;
    float qa2 = a2.x*a2.x + a2.y*a2.y + a2.z*a2.z + a2.w*a2.w;
    float qb0 = b0.x*b0.x + b0.y*b0.y + b0.z*b0.z + b0.w*b0.w;
    float qb1 = b1.x*b1.x + b1.y*b1.y + b1.z*b1.z + b1.w*b1.w;
    float qb2 = b2.x*b2.x + b2.y*b2.y + b2.z*b2.z + b2.w*b2.w;

    #pragma unroll
    for (int o = 4; o >= 1; o >>= 1) {
        qa0 += __shfl_xor_sync(0xffffffffu, qa0, o, 8);
        qa1 += __shfl_xor_sync(0xffffffffu, qa1, o, 8);
        qa2 += __shfl_xor_sync(0xffffffffu, qa2, o, 8);
        qb0 += __shfl_xor_sync(0xffffffffu, qb0, o, 8);
        qb1 += __shfl_xor_sync(0xffffffffu, qb1, o, 8);
        qb2 += __shfl_xor_sync(0xffffffffu, qb2, o, 8);
    }
    float xa0 = 1.0f/qa0, xa1 = 1.0f/qa1, xa2 = 1.0f/qa2;
    float xb0 = 1.0f/qb0, xb1 = 1.0f/qb1, xb2 = 1.0f/qb2;

    float sa = xa0 + xa1 + xa2,  pa = xa0 * xa1 * xa2;
    float sb = xb0 + xb1 + xb2,  pb = xb0 * xb1 * xb2;
    sa += __shfl_xor_sync(0xffffffffu, sa, 8);
    sb += __shfl_xor_sync(0xffffffffu, sb, 8);
    sa += __shfl_xor_sync(0xffffffffu, sa, 16);
    sb += __shfl_xor_sync(0xffffffffu, sb, 16);
    pa *= __shfl_xor_sync(0xffffffffu, pa, 8);
    pb *= __shfl_xor_sync(0xffffffffu, pb, 8);
    pa *= __shfl_xor_sync(0xffffffffu, pa, 16);
    pb *= __shfl_xor_sync(0xffffffffu, pb, 16);

    sa = fmaxf(sa, 1e-12f);
    sb = fmaxf(sb, 1e-12f);
    float sa2 = sa*sa, sa4 = sa2*sa2, sa8 = sa4*sa4;
    float sb2 = sb*sb, sb4 = sb2*sb2, sb8 = sb4*sb4;
    if (lane == 0) {
        g_bn3[row0]     = pa / (sa8 * sa4);
        g_bn3[row0 + 1] = pb / (sb8 * sb4);
    }
}

// ---------------------------------------------------------------------------
// Kernel 2 (unchanged): normalize over B, invert, normalize over N.
// ---------------------------------------------------------------------------
__global__ void norm_kernel() {
    int b = blockIdx.x;
    int n = threadIdx.x;

    float csum = 0.0f;
    #pragma unroll
    for (int bb = 0; bb < BB; bb++) csum += fabsf(g_bn3[bb * NN + n]);
    csum = fmaxf(csum, 1e-12f);

    float bn4 = g_bn3[b * NN + n] / csum;
    float bn5 = 1.0f / bn4;

    float r = fabsf(bn5);
    #pragma unroll
    for (int o = 16; o >= 1; o >>= 1) r += __shfl_xor_sync(0xffffffffu, r, o, 32);

    __shared__ float part[32];
    __shared__ float total;
    int wid = threadIdx.x >> 5, lane = threadIdx.x & 31;
    if (lane == 0) part[wid] = r;
    __syncthreads();
    if (wid == 0) {
        float v = part[lane];
        #pragma unroll
        for (int o = 16; o >= 1; o >>= 1) v += __shfl_xor_sync(0xffffffffu, v, o, 32);
        if (lane == 0) total = fmaxf(v, 1e-12f);
    }
    __syncthreads();

    g_bn6[b * NN + n] = bn5 / total;
}

// ---------------------------------------------------------------------------
// Kernel 2b: prep — convert atom and W to fp16 (one kernel, branch by block).
// ---------------------------------------------------------------------------
__global__ void prep_kernel(const float* __restrict__ atom,
                            const float* __restrict__ W) {
    int bid = blockIdx.x;
    if (bid < 1024) {
        // atom: 2,097,152 floats; 2048 per block, 8 per thread
        int base = bid * 2048 + threadIdx.x * 8;
        float4 f0 = *(const float4*)(atom + base);
        float4 f1 = *(const float4*)(atom + base + 4);
        uint4 packed;
        packed.x = h2_to_u(__floats2half2_rn(f0.x, f0.y));
        packed.y = h2_to_u(__floats2half2_rn(f0.z, f0.w));
        packed.z = h2_to_u(__floats2half2_rn(f1.x, f1.y));
        packed.w = h2_to_u(__floats2half2_rn(f1.z, f1.w));
        *(uint4*)(g_atom_h + base) = packed;
    } else {
        // W: 16384 floats; blocks 1024..1087, 1 per thread
        int i = (bid - 1024) * 256 + threadIdx.x;
        g_Wh[i] = __float2half_rn(W[i]);
    }
}

// ---------------------------------------------------------------------------
// Kernel 3: gather(fp16) + scale -> smem dup-pair half2 rows, HFMA2 GEMM.
// Grid (8,16) = 128 CTAs (one wave), 256 threads.
// Warp w owns rows 16w..16w+15 end-to-end -> __syncwarp between phases.
// sU row r: 128 uint32 dup pairs (u_k,u_k) = 512 B. sWh: [k][j] half, 256B/row.
// GEMM: thread = 8 rows x 8 cols; per 4-k chunk: 12 LDS.128 + 128 HFMA2.
// ---------------------------------------------------------------------------
#define SM_W_BYTES (FA * FO * 2)            // 32 KB
#define SM_U_BYTES (128 * FA * 4)           // 64 KB (dup pairs)
#define SMEM_TOTAL (SM_W_BYTES + SM_U_BYTES)

__global__ void __launch_bounds__(256)
main_kernel(const int* __restrict__ adj,
            const float* __restrict__ bias,
            float* __restrict__ out) {
    extern __shared__ char smem[];
    __half* sWh  = (__half*)smem;                       // [k][j]
    char*   sU   = smem + SM_W_BYTES;                   // dup-pair rows, 512 B each

    int b   = blockIdx.y;
    int n0  = blockIdx.x * 128;
    int tid = threadIdx.x;
    int wid = tid >> 5, lane = tid & 31;
    int stride = g_is64 ? 2 : 1;

    // Load W(half) into smem: 32 KB, 8 x uint4 per thread
    {
        const uint4* src = (const uint4*)g_Wh;
        uint4* dst = (uint4*)sWh;
        #pragma unroll
        for (int i = 0; i < 8; i++) dst[tid + i * 256] = src[tid + i * 256];
    }
    __syncthreads();

    // ---- Phase A: fp16 gather + scale, write dup-pair half2 rows
    {
        const __half* atomBh = g_atom_h + (size_t)b * NN * FA;
        const __half2 inv12h = __float2half2_rn(1.0f / 12.0f);
        #pragma unroll 2
        for (int i = 0; i < 16; i++) {
            int r = wid * 16 + i;
            int n = n0 + r;
            const int* adjr = adj + (size_t)(b * NN + n) * MM * stride;
            uint2 selfw = *(const uint2*)(atomBh + (size_t)n * FA + lane * 4);
            __half2 a0 = u_to_h2(selfw.x);
            __half2 a1 = u_to_h2(selfw.y);
            __half2 s0 = __float2half2_rn(0.0f);
            __half2 s1 = __float2half2_rn(0.0f);
            #pragma unroll
            for (int m = 0; m < MM; m++) {
                int idx = adjr[m * stride] & (NN - 1);
                uint2 vw = *(const uint2*)(atomBh + (size_t)idx * FA + lane * 4);
                s0 = __hadd2(s0, u_to_h2(vw.x));
                s1 = __hadd2(s1, u_to_h2(vw.y));
            }
            __half2 bnh = __float2half2_rn(g_bn6[b * NN + n]);
            __half2 u0 = __hmul2(__hfma2(s0, inv12h, a0), bnh);
            __half2 u1 = __hmul2(__hfma2(s1, inv12h, a1), bnh);
            uint4 dupw;
            dupw.x = h2_to_u(__half2half2(__low2half(u0)));
            dupw.y = h2_to_u(__half2half2(__high2half(u0)));
            dupw.z = h2_to_u(__half2half2(__low2half(u1)));
            dupw.w = h2_to_u(__half2half2(__high2half(u1)));
            *(uint4*)(sU + (size_t)r * 512 + lane * 16) = dupw;
        }
    }
    __syncwarp();

    // ---- Phase B: HFMA2 GEMM, 8 rows x 8 cols per thread
    int ty = tid >> 4;        // 0..15 -> rows [ty*8, ty*8+8) (warp-local rows)
    int tx = tid & 15;        // 0..15 -> cols [tx*8, tx*8+8)
    int r0 = ty * 8;
    int c0 = tx * 8;

    __half2 acc[8][4];
    #pragma unroll
    for (int i = 0; i < 8; i++)
        #pragma unroll
        for (int j = 0; j < 4; j++) acc[i][j] = __float2half2_rn(0.0f);

    #pragma unroll 4
    for (int k0 = 0; k0 < FA; k0 += 4) {
        // w rows k0..k0+3, cols c0..c0+7: 4 x uint4 (4 half2 each)
        uint32_t wv[4][4];
        #pragma unroll
        for (int kk = 0; kk < 4; kk++) {
            uint4 t = *(const uint4*)((const char*)sWh + (size_t)(k0 + kk) * 256 + tx * 16);
            wv[kk][0] = t.x; wv[kk][1] = t.y; wv[kk][2] = t.z; wv[kk][3] = t.w;
        }
        #pragma unroll
        for (int i = 0; i < 8; i++) {
            // dup pairs for rows r0+i, k = k0..k0+3
            uint4 uv = *(const uint4*)(sU + (size_t)(r0 + i) * 512 + k0 * 4);
            uint32_t ud[4] = {uv.x, uv.y, uv.z, uv.w};
            #pragma unroll
            for (int kk = 0; kk < 4; kk++) {
                __half2 u2 = u_to_h2(ud[kk]);
                acc[i][0] = __hfma2(u2, u_to_h2(wv[kk][0]), acc[i][0]);
                acc[i][1] = __hfma2(u2, u_to_h2(wv[kk][1]), acc[i][1]);
                acc[i][2] = __hfma2(u2, u_to_h2(wv[kk][2]), acc[i][2]);
                acc[i][3] = __hfma2(u2, u_to_h2(wv[kk][3]), acc[i][3]);
            }
        }
    }

    // Epilogue: fp32 bias + relu + coalesced float4 stores
    float4 bi0 = *(const float4*)(bias + c0);
    float4 bi1 = *(const float4*)(bias + c0 + 4);

    #pragma unroll
    for (int i = 0; i < 8; i++) {
        int n = n0 + r0 + i;
        float2 p0 = __half22float2(acc[i][0]);
        float2 p1 = __half22float2(acc[i][1]);
        float2 p2 = __half22float2(acc[i][2]);
        float2 p3 = __half22float2(acc[i][3]);
        float4 o0, o1;
        o0.x = fmaxf(p0.x + bi0.x, 0.0f);
        o0.y = fmaxf(p0.y + bi0.y, 0.0f);
        o0.z = fmaxf(p1.x + bi0.z, 0.0f);
        o0.w = fmaxf(p1.y + bi0.w, 0.0f);
        o1.x = fmaxf(p2.x + bi1.x, 0.0f);
        o1.y = fmaxf(p2.y + bi1.y, 0.0f);
        o1.z = fmaxf(p3.x + bi1.z, 0.0f);
        o1.w = fmaxf(p3.y + bi1.w, 0.0f);
        float* op = out + (size_t)(b * NN + n) * FO + c0;
        *(float4*)(op)     = o0;
        *(float4*)(op + 4) = o1;
    }
}

// ---------------------------------------------------------------------------
extern "C" void kernel_launch(void* const* d_in, const int* in_sizes, int n_in,
                              void* d_out, int out_size) {
    const float* atom = (const float*)d_in[0];
    const float* bond = (const float*)d_in[1];
    const int*   adj  = (const int*)d_in[2];
    const float* W    = (const float*)d_in[3];
    const float* bias = (const float*)d_in[4];
    float*       out  = (float*)d_out;

    bond_kernel<<<1024, 256>>>(bond, adj);
    prep_kernel<<<1088, 256>>>(atom, W);
    norm_kernel<<<BB, NN>>>();

    cudaFuncSetAttribute(main_kernel, cudaFuncAttributeMaxDynamicSharedMemorySize,
                         SMEM_TOTAL);
    main_kernel<<<dim3(8, BB), 256, SMEM_TOTAL>>>(adj, bias, out);
}